// round 11
// baseline (speedup 1.0000x reference)
#include <cuda_runtime.h>
#include <math.h>

#define B_ 4
#define N_ 4096
#define D_ 768
#define H_ 12
#define HD_ 64
#define E_ 160
#define NC_ 32
#define NU_ 128
#define CH_ 3072
#define OH_ 768
#define BH_ 48

typedef unsigned long long u64;

__device__ float g_qn[H_ * E_ * HD_];
__device__ float g_logits[(size_t)BH_ * N_ * E_];
__device__ float g_Z[BH_ * E_];
__device__ float g_slots[B_ * E_ * D_];
__device__ float g_hid[B_ * NC_ * CH_];
__device__ float g_hid2[B_ * NU_ * OH_];
__device__ float g_eo[B_ * E_ * D_];

__device__ __forceinline__ void ffma2(u64 &a, u64 x, u64 y) {
    asm("fma.rn.f32x2 %0, %1, %2, %0;" : "+l"(a) : "l"(x), "l"(y));
}
__device__ __forceinline__ float sum2(u64 v) {
    float lo, hi;
    asm("mov.b64 {%0,%1}, %2;" : "=f"(lo), "=f"(hi) : "l"(v));
    return lo + hi;
}
__device__ __forceinline__ float gelu_exact(float v) {
    return 0.5f * v * (1.0f + erff(v * 0.70710678f));
}

__global__ void k_zero() {
    int i = blockIdx.x * 256 + threadIdx.x;
    if (i < B_ * E_ * D_) { g_slots[i] = 0.f; g_eo[i] = 0.f; }
    if (i < BH_ * E_) g_Z[i] = 0.f;
}

__global__ void k_prep_q(const float* __restrict__ phi, const float* __restrict__ qg,
                         const float* __restrict__ qb, const float* __restrict__ lw,
                         const float* __restrict__ lb) {
    int gw = (blockIdx.x * blockDim.x + threadIdx.x) >> 5, lane = threadIdx.x & 31;
    if (gw >= H_ * E_) return;
    int h = gw / E_, e = gw % E_, d0 = lane, d1 = lane + 32;
    float t0 = phi[(size_t)e * D_ + h * HD_ + d0] * qg[d0] + qb[d0];
    float t1 = phi[(size_t)e * D_ + h * HD_ + d1] * qg[d1] + qb[d1];
    float s = t0 + t1;
#pragma unroll
    for (int o = 16; o; o >>= 1) s += __shfl_xor_sync(~0u, s, o);
    float m = s * (1.f / 64.f), c0 = t0 - m, c1 = t1 - m, v = c0 * c0 + c1 * c1;
#pragma unroll
    for (int o = 16; o; o >>= 1) v += __shfl_xor_sync(~0u, v, o);
    float inv = rsqrtf(v * (1.f / 64.f) + 1e-5f);
    float y0 = c0 * inv * lw[d0] + lb[d0], y1 = c1 * inv * lw[d1] + lb[d1];
    float ss = y0 * y0 + y1 * y1;
#pragma unroll
    for (int o = 16; o; o >>= 1) ss += __shfl_xor_sync(~0u, ss, o);
    float r = 1.f / (sqrtf(ss) + 1e-6f);
    g_qn[gw * HD_ + d0] = y0 * r;
    g_qn[gw * HD_ + d1] = y1 * r;
}

__global__ __launch_bounds__(512) void k_logits(const float* __restrict__ x,
                                                const float* __restrict__ kg,
                                                const float* __restrict__ kb,
                                                const float* __restrict__ s0p) {
    extern __shared__ float sm[];
    float* s_k = sm;
    float* s_q = sm + 64 * 66;
    float* s_inv = s_q + 160 * 66;
    int tid = threadIdx.x, n0 = blockIdx.x * 64, bh = blockIdx.y;
    int b = bh / H_, h = bh % H_;
#pragma unroll
    for (int i = 0; i < 8; i++) {
        int idx = tid + 512 * i, t = idx >> 6, d = idx & 63;
        s_k[t * 66 + d] = x[((size_t)(b * N_ + n0 + t)) * D_ + h * HD_ + d] * kg[d] + kb[d];
    }
#pragma unroll
    for (int i = 0; i < 20; i++) {
        int idx = tid + 512 * i, e = idx >> 6, d = idx & 63;
        s_q[e * 66 + d] = g_qn[(h * E_ + e) * HD_ + d];
    }
    __syncthreads();
    if (tid < 64) {
        float ss = 0.f;
#pragma unroll
        for (int d = 0; d < 64; d++) { float v = s_k[tid * 66 + d]; ss += v * v; }
        s_inv[tid] = 1.f / (sqrtf(ss) + 1e-6f);
    }
    __syncthreads();
#pragma unroll
    for (int i = 0; i < 8; i++) {
        int idx = tid + 512 * i, t = idx >> 6, d = idx & 63;
        s_k[t * 66 + d] *= s_inv[t];
    }
    __syncthreads();
    int lane = tid & 31, eg = tid >> 5;
    u64 acc[2][10];
#pragma unroll
    for (int a = 0; a < 2; a++)
#pragma unroll
        for (int j = 0; j < 10; j++) acc[a][j] = 0ull;
    const float* k0p = s_k + lane * 66;
    const float* k1p = s_k + (lane + 32) * 66;
#pragma unroll 4
    for (int dp = 0; dp < 32; dp++) {
        u64 k0 = *(const u64*)(k0p + 2 * dp), k1 = *(const u64*)(k1p + 2 * dp);
#pragma unroll
        for (int j = 0; j < 10; j++) {
            u64 q = *(const u64*)(s_q + (eg + 16 * j) * 66 + 2 * dp);
            ffma2(acc[0][j], k0, q);
            ffma2(acc[1][j], k1, q);
        }
    }
    float inv0 = 1.f / __ldg(s0p);
    float l0[10], l1[10], zs[10];
#pragma unroll
    for (int j = 0; j < 10; j++) {
        l0[j] = sum2(acc[0][j]);
        l1[j] = sum2(acc[1][j]);
        zs[j] = __expf(l0[j] * inv0) + __expf(l1[j] * inv0);
#pragma unroll
        for (int o = 16; o; o >>= 1) zs[j] += __shfl_xor_sync(~0u, zs[j], o);
    }
    if (lane == 0)
#pragma unroll
        for (int j = 0; j < 10; j++) atomicAdd(&g_Z[bh * E_ + eg + 16 * j], zs[j]);
    __syncthreads();
    float* s_o = sm;
#pragma unroll
    for (int j = 0; j < 10; j++) {
        s_o[lane * 161 + eg + 16 * j] = l0[j];
        s_o[(lane + 32) * 161 + eg + 16 * j] = l1[j];
    }
    __syncthreads();
    size_t base = ((size_t)bh * N_ + n0) * E_;
#pragma unroll
    for (int i = 0; i < 20; i++) {
        int idx = tid + 512 * i, t = idx / 160, e = idx - t * 160;
        g_logits[base + idx] = s_o[t * 161 + e];
    }
}

// slots: full 160e x 64hd per block, 1024-token chunk; tile 10e x 4hd/thread
__global__ __launch_bounds__(256) void k_slots(const float* __restrict__ x,
                                               const float* __restrict__ s0p) {
    __shared__ float s_p[32 * 162];
    __shared__ float s_x[32 * 68];
    int tid = threadIdx.x, bh = blockIdx.x, nc = blockIdx.y;
    int b = bh / H_, h = bh % H_;
    float inv0 = 1.f / __ldg(s0p);
    int te = tid & 15, th = tid >> 4;
    u64 acc[5][4];
#pragma unroll
    for (int j = 0; j < 5; j++)
#pragma unroll
        for (int c = 0; c < 4; c++) acc[j][c] = 0ull;
    for (int sb = 0; sb < 32; sb++) {
        int nb = nc * 1024 + sb * 32;
        __syncthreads();
#pragma unroll
        for (int i = 0; i < 20; i++) {
            int idx = tid + 256 * i;
            int n = idx / 160, e = idx - n * 160;
            s_p[n * 162 + e] = __expf(g_logits[((size_t)bh * N_ + nb + n) * E_ + e] * inv0);
        }
#pragma unroll
        for (int i = 0; i < 8; i++) {
            int idx = tid + 256 * i, n = idx >> 6, d = idx & 63;
            s_x[n * 68 + d] = x[((size_t)(b * N_ + nb + n)) * D_ + h * HD_ + d];
        }
        __syncthreads();
#pragma unroll 2
        for (int n = 0; n < 32; n++) {
            u64 xd[4];
#pragma unroll
            for (int c = 0; c < 4; c++) {
                float xv = s_x[n * 68 + th * 4 + c];
                asm("mov.b64 %0, {%1,%1};" : "=l"(xd[c]) : "f"(xv));
            }
#pragma unroll
            for (int j = 0; j < 5; j++) {
                u64 pv = *(const u64*)(s_p + n * 162 + te * 10 + 2 * j);
#pragma unroll
                for (int c = 0; c < 4; c++) ffma2(acc[j][c], pv, xd[c]);
            }
        }
    }
#pragma unroll
    for (int j = 0; j < 5; j++)
#pragma unroll
        for (int c = 0; c < 4; c++) {
            float lo, hi;
            asm("mov.b64 {%0,%1}, %2;" : "=f"(lo), "=f"(hi) : "l"(acc[j][c]));
            int e = te * 10 + 2 * j, hd = th * 4 + c;
            atomicAdd(&g_slots[((size_t)(b * E_ + e)) * D_ + h * HD_ + hd], lo);
            atomicAdd(&g_slots[((size_t)(b * E_ + e + 1)) * D_ + h * HD_ + hd], hi);
        }
}

__global__ void k_finalize() {
    int i = blockIdx.x * 256 + threadIdx.x;
    if (i >= B_ * E_ * D_) return;
    int b = i / (E_ * D_), r = i - b * E_ * D_, e = r / D_, d = r - e * D_;
    g_slots[i] /= g_Z[(b * H_ + (d >> 6)) * E_ + e];
}

// MLP layer1: float4 weight streaming, 4 m-cols x 4 batches per thread
__global__ __launch_bounds__(128) void k_mlp1(const float* __restrict__ w1,
                                              const float* __restrict__ b1,
                                              int M, int El, int e0, int core) {
    __shared__ float s_in[4 * 768];
    int tid = threadIdx.x, e = blockIdx.x;
    int m = (blockIdx.y * 128 + tid) * 4;
    for (int idx = tid; idx < 4 * 768; idx += 128) {
        int b = idx / 768, d = idx - b * 768;
        s_in[idx] = g_slots[((size_t)(b * E_ + e0 + e)) * D_ + d];
    }
    __syncthreads();
    if (m >= M) return;
    float a[4][4];
#pragma unroll
    for (int bb = 0; bb < 4; bb++)
#pragma unroll
        for (int c = 0; c < 4; c++) a[bb][c] = 0.f;
    size_t st4 = M >> 2;
    const float4* wp = (const float4*)w1 + (size_t)e * 768 * st4 + (m >> 2);
#pragma unroll 1
    for (int k0 = 0; k0 < 768; k0 += 8) {
        float4 wv[8];
#pragma unroll
        for (int i = 0; i < 8; i++) wv[i] = wp[(size_t)(k0 + i) * st4];
#pragma unroll
        for (int i = 0; i < 8; i++)
#pragma unroll
            for (int bb = 0; bb < 4; bb++) {
                float sv = s_in[bb * 768 + k0 + i];
                a[bb][0] = fmaf(sv, wv[i].x, a[bb][0]);
                a[bb][1] = fmaf(sv, wv[i].y, a[bb][1]);
                a[bb][2] = fmaf(sv, wv[i].z, a[bb][2]);
                a[bb][3] = fmaf(sv, wv[i].w, a[bb][3]);
            }
    }
    float4 bv = *(const float4*)(b1 + (size_t)e * M + m);
    float* o = core ? g_hid : g_hid2;
#pragma unroll
    for (int bb = 0; bb < 4; bb++) {
        float4 r;
        r.x = gelu_exact(a[bb][0] + bv.x);
        r.y = gelu_exact(a[bb][1] + bv.y);
        r.z = gelu_exact(a[bb][2] + bv.z);
        r.w = gelu_exact(a[bb][3] + bv.w);
        *(float4*)(o + ((size_t)(bb * El + e)) * M + m) = r;
    }
}

// MLP layer2: float4 streaming, K-split, atomics into g_eo
__global__ __launch_bounds__(128) void k_mlp2(const float* __restrict__ w2,
                                              const float* __restrict__ b2,
                                              int K, int El, int e0, int core) {
    __shared__ float s_h[4 * 768];
    int tid = threadIdx.x, e = blockIdx.x, ks = blockIdx.z;
    int m = (blockIdx.y * 128 + tid) * 4;
    const float* hid = core ? g_hid : g_hid2;
    for (int idx = tid; idx < 4 * 768; idx += 128) {
        int b = idx / 768, d = idx - b * 768;
        s_h[idx] = hid[((size_t)(b * El + e)) * K + ks * 768 + d];
    }
    __syncthreads();
    if (m >= 768) return;
    float a[4][4];
    float4 bv = make_float4(0.f, 0.f, 0.f, 0.f);
    if (ks == 0) bv = *(const float4*)(b2 + (size_t)e * 768 + m);
#pragma unroll
    for (int bb = 0; bb < 4; bb++) {
        a[bb][0] = bv.x; a[bb][1] = bv.y; a[bb][2] = bv.z; a[bb][3] = bv.w;
    }
    const float4* wp = (const float4*)w2 + ((size_t)e * K + ks * 768) * 192 + (m >> 2);
#pragma unroll 1
    for (int k0 = 0; k0 < 768; k0 += 8) {
        float4 wv[8];
#pragma unroll
        for (int i = 0; i < 8; i++) wv[i] = wp[(size_t)(k0 + i) * 192];
#pragma unroll
        for (int i = 0; i < 8; i++)
#pragma unroll
            for (int bb = 0; bb < 4; bb++) {
                float sv = s_h[bb * 768 + k0 + i];
                a[bb][0] = fmaf(sv, wv[i].x, a[bb][0]);
                a[bb][1] = fmaf(sv, wv[i].y, a[bb][1]);
                a[bb][2] = fmaf(sv, wv[i].z, a[bb][2]);
                a[bb][3] = fmaf(sv, wv[i].w, a[bb][3]);
            }
    }
#pragma unroll
    for (int bb = 0; bb < 4; bb++)
#pragma unroll
        for (int c = 0; c < 4; c++)
            atomicAdd(&g_eo[((size_t)(bb * E_ + e0 + e)) * D_ + m + c], a[bb][c]);
}

__global__ __launch_bounds__(256) void k_combine(float* __restrict__ out,
                                                 const float* __restrict__ s1p) {
    extern __shared__ float sm[];
    float* s_eoT = sm;
    float* s_w = sm + 64 * 162;
    int tid = threadIdx.x, lane = tid & 31, wid = tid >> 5;
    int n0 = blockIdx.x * 64, bh = blockIdx.y, b = bh / H_, h = bh % H_;
#pragma unroll
    for (int i = 0; i < 40; i++) {
        int idx = tid + 256 * i, e = idx >> 6, hd = idx & 63;
        s_eoT[hd * 162 + e] = g_eo[((size_t)(b * E_ + e)) * D_ + h * HD_ + hd];
    }
    float inv1 = 1.f / __ldg(s1p);
    for (int i = 0; i < 8; i++) {
        int t = wid * 8 + i;
        const float* lp = g_logits + ((size_t)bh * N_ + n0 + t) * E_;
        float v[5];
#pragma unroll
        for (int j = 0; j < 5; j++) v[j] = lp[lane + 32 * j] * inv1;
        float mx = fmaxf(fmaxf(fmaxf(v[0], v[1]), fmaxf(v[2], v[3])), v[4]);
#pragma unroll
        for (int o = 16; o; o >>= 1) mx = fmaxf(mx, __shfl_xor_sync(~0u, mx, o));
#pragma unroll
        for (int j = 0; j < 5; j++) v[j] = (v[j] - mx) * 0.5f;
        float tau = -1.f;
        for (int it = 0; it < 30; it++) {
            float s1 = 0.f, s2 = 0.f;
#pragma unroll
            for (int j = 0; j < 5; j++) {
                float d = fmaxf(v[j] - tau, 0.f);
                s1 += d;
                s2 = fmaf(d, d, s2);
            }
#pragma unroll
            for (int o = 16; o; o >>= 1) {
                s1 += __shfl_xor_sync(~0u, s1, o);
                s2 += __shfl_xor_sync(~0u, s2, o);
            }
            float dt = (s2 - 1.f) / (2.f * s1);
            tau += dt;
            if (dt < 1e-7f) break;
        }
#pragma unroll
        for (int j = 0; j < 5; j++) {
            float d = fmaxf(v[j] - tau, 0.f);
            s_w[t * 160 + lane + 32 * j] = d * d;
        }
    }
    __syncthreads();
    int hq = tid & 15, tq = tid >> 4;
    u64 acc[4][4];
#pragma unroll
    for (int tt = 0; tt < 4; tt++)
#pragma unroll
        for (int c = 0; c < 4; c++) acc[tt][c] = 0ull;
#pragma unroll 2
    for (int ep = 0; ep < 80; ep++) {
        u64 wv[4], ev[4];
#pragma unroll
        for (int tt = 0; tt < 4; tt++) wv[tt] = *(const u64*)(s_w + (tq * 4 + tt) * 160 + 2 * ep);
#pragma unroll
        for (int c = 0; c < 4; c++) ev[c] = *(const u64*)(s_eoT + (hq * 4 + c) * 162 + 2 * ep);
#pragma unroll
        for (int tt = 0; tt < 4; tt++)
#pragma unroll
            for (int c = 0; c < 4; c++) ffma2(acc[tt][c], wv[tt], ev[c]);
    }
#pragma unroll
    for (int tt = 0; tt < 4; tt++) {
        float4 r = make_float4(sum2(acc[tt][0]), sum2(acc[tt][1]),
                               sum2(acc[tt][2]), sum2(acc[tt][3]));
        *(float4*)(out + ((size_t)(b * N_ + n0 + tq * 4 + tt)) * D_ + h * HD_ + hq * 4) = r;
    }
}

extern "C" void kernel_launch(void* const* d_in, const int* in_sizes, int n_in,
                              void* d_out, int out_size) {
    const float* x   = (const float*)d_in[0];
    const float* phi = (const float*)d_in[1];
    const float* kgm = (const float*)d_in[2];
    const float* kbt = (const float*)d_in[3];
    const float* qgm = (const float*)d_in[4];
    const float* qbt = (const float*)d_in[5];
    const float* lnw = (const float*)d_in[6];
    const float* lnb = (const float*)d_in[7];
    const float* s0  = (const float*)d_in[8];
    const float* s1  = (const float*)d_in[9];
    const float* cw1 = (const float*)d_in[10];
    const float* cb1 = (const float*)d_in[11];
    const float* cw2 = (const float*)d_in[12];
    const float* cb2 = (const float*)d_in[13];
    const float* ow1 = (const float*)d_in[14];
    const float* ob1 = (const float*)d_in[15];
    const float* ow2 = (const float*)d_in[16];
    const float* ob2 = (const float*)d_in[17];
    float* out = (float*)d_out;

    const int SM_LOG = (64 * 66 + 160 * 66 + 64) * 4;
    const int SM_CMB = (64 * 162 + 64 * 160) * 4;
    cudaFuncSetAttribute(k_logits, cudaFuncAttributeMaxDynamicSharedMemorySize, SM_LOG);
    cudaFuncSetAttribute(k_combine, cudaFuncAttributeMaxDynamicSharedMemorySize, SM_CMB);

    k_zero<<<1920, 256>>>();
    k_prep_q<<<60, 1024>>>(phi, qgm, qbt, lnw, lnb);
    k_logits<<<dim3(64, 48), 512, SM_LOG>>>(x, kgm, kbt, s0);
    k_slots<<<dim3(48, 4), 256>>>(x, s0);
    k_finalize<<<1920, 256>>>();
    k_mlp1<<<dim3(NC_, 6), 128>>>(cw1, cb1, CH_, NC_, 0, 1);
    k_mlp1<<<dim3(NU_, 2), 128>>>(ow1, ob1, OH_, NU_, NC_, 0);
    k_mlp2<<<dim3(NC_, 2, 4), 128>>>(cw2, cb2, CH_, NC_, 0, 1);
    k_mlp2<<<dim3(NU_, 2, 1), 128>>>(ow2, ob2, OH_, NU_, NC_, 0);
    k_combine<<<dim3(64, 48), 256, SM_CMB>>>(out, s1);
}

// round 12
// speedup vs baseline: 1.3261x; 1.3261x over previous
#include <cuda_runtime.h>
#include <math.h>

#define B_ 4
#define N_ 4096
#define D_ 768
#define H_ 12
#define HD_ 64
#define E_ 160
#define NC_ 32
#define NU_ 128
#define CH_ 3072
#define OH_ 768
#define BH_ 48

typedef unsigned long long u64;

__device__ float g_qn[H_ * E_ * HD_];
__device__ float g_logits[(size_t)BH_ * N_ * E_];
__device__ float g_Z[BH_ * E_];
__device__ float g_slots[B_ * E_ * D_];
__device__ float g_hid[B_ * NC_ * CH_];
__device__ float g_hid2[B_ * NU_ * OH_];
__device__ float g_eo[B_ * E_ * D_];

__device__ __forceinline__ void ffma2(u64 &a, u64 x, u64 y) {
    asm("fma.rn.f32x2 %0, %1, %2, %0;" : "+l"(a) : "l"(x), "l"(y));
}
__device__ __forceinline__ u64 pack2(float lo, float hi) {
    u64 r;
    asm("mov.b64 %0, {%1,%2};" : "=l"(r) : "f"(lo), "f"(hi));
    return r;
}
__device__ __forceinline__ void unpack2(u64 v, float &lo, float &hi) {
    asm("mov.b64 {%0,%1}, %2;" : "=f"(lo), "=f"(hi) : "l"(v));
}
__device__ __forceinline__ float sum2(u64 v) {
    float lo, hi; unpack2(v, lo, hi); return lo + hi;
}
__device__ __forceinline__ float gelu_exact(float v) {
    return 0.5f * v * (1.0f + erff(v * 0.70710678f));
}

__global__ void k_zero() {
    int i = blockIdx.x * 256 + threadIdx.x;
    if (i < B_ * E_ * D_) { g_slots[i] = 0.f; g_eo[i] = 0.f; }
    if (i < BH_ * E_) g_Z[i] = 0.f;
}

__global__ void k_prep_q(const float* __restrict__ phi, const float* __restrict__ qg,
                         const float* __restrict__ qb, const float* __restrict__ lw,
                         const float* __restrict__ lb) {
    int gw = (blockIdx.x * blockDim.x + threadIdx.x) >> 5, lane = threadIdx.x & 31;
    if (gw >= H_ * E_) return;
    int h = gw / E_, e = gw % E_, d0 = lane, d1 = lane + 32;
    float t0 = phi[(size_t)e * D_ + h * HD_ + d0] * qg[d0] + qb[d0];
    float t1 = phi[(size_t)e * D_ + h * HD_ + d1] * qg[d1] + qb[d1];
    float s = t0 + t1;
#pragma unroll
    for (int o = 16; o; o >>= 1) s += __shfl_xor_sync(~0u, s, o);
    float m = s * (1.f / 64.f), c0 = t0 - m, c1 = t1 - m, v = c0 * c0 + c1 * c1;
#pragma unroll
    for (int o = 16; o; o >>= 1) v += __shfl_xor_sync(~0u, v, o);
    float inv = rsqrtf(v * (1.f / 64.f) + 1e-5f);
    float y0 = c0 * inv * lw[d0] + lb[d0], y1 = c1 * inv * lw[d1] + lb[d1];
    float ss = y0 * y0 + y1 * y1;
#pragma unroll
    for (int o = 16; o; o >>= 1) ss += __shfl_xor_sync(~0u, ss, o);
    float r = 1.f / (sqrtf(ss) + 1e-6f);
    g_qn[gw * HD_ + d0] = y0 * r;
    g_qn[gw * HD_ + d1] = y1 * r;
}

__global__ __launch_bounds__(512) void k_logits(const float* __restrict__ x,
                                                const float* __restrict__ kg,
                                                const float* __restrict__ kb,
                                                const float* __restrict__ s0p) {
    extern __shared__ float sm[];
    float* s_k = sm;
    float* s_q = sm + 64 * 66;
    float* s_inv = s_q + 160 * 66;
    int tid = threadIdx.x, n0 = blockIdx.x * 64, bh = blockIdx.y;
    int b = bh / H_, h = bh % H_;
#pragma unroll
    for (int i = 0; i < 8; i++) {
        int idx = tid + 512 * i, t = idx >> 6, d = idx & 63;
        s_k[t * 66 + d] = x[((size_t)(b * N_ + n0 + t)) * D_ + h * HD_ + d] * kg[d] + kb[d];
    }
#pragma unroll
    for (int i = 0; i < 20; i++) {
        int idx = tid + 512 * i, e = idx >> 6, d = idx & 63;
        s_q[e * 66 + d] = g_qn[(h * E_ + e) * HD_ + d];
    }
    __syncthreads();
    if (tid < 64) {
        float ss = 0.f;
#pragma unroll
        for (int d = 0; d < 64; d++) { float v = s_k[tid * 66 + d]; ss += v * v; }
        s_inv[tid] = 1.f / (sqrtf(ss) + 1e-6f);
    }
    __syncthreads();
#pragma unroll
    for (int i = 0; i < 8; i++) {
        int idx = tid + 512 * i, t = idx >> 6, d = idx & 63;
        s_k[t * 66 + d] *= s_inv[t];
    }
    __syncthreads();
    int lane = tid & 31, eg = tid >> 5;
    u64 acc[2][10];
#pragma unroll
    for (int a = 0; a < 2; a++)
#pragma unroll
        for (int j = 0; j < 10; j++) acc[a][j] = 0ull;
    const float* k0p = s_k + lane * 66;
    const float* k1p = s_k + (lane + 32) * 66;
#pragma unroll 4
    for (int dp = 0; dp < 32; dp++) {
        u64 k0 = *(const u64*)(k0p + 2 * dp), k1 = *(const u64*)(k1p + 2 * dp);
#pragma unroll
        for (int j = 0; j < 10; j++) {
            u64 q = *(const u64*)(s_q + (eg + 16 * j) * 66 + 2 * dp);
            ffma2(acc[0][j], k0, q);
            ffma2(acc[1][j], k1, q);
        }
    }
    float inv0 = 1.f / __ldg(s0p);
    float l0[10], l1[10], zs[10];
#pragma unroll
    for (int j = 0; j < 10; j++) {
        l0[j] = sum2(acc[0][j]);
        l1[j] = sum2(acc[1][j]);
        zs[j] = __expf(l0[j] * inv0) + __expf(l1[j] * inv0);
#pragma unroll
        for (int o = 16; o; o >>= 1) zs[j] += __shfl_xor_sync(~0u, zs[j], o);
    }
    if (lane == 0)
#pragma unroll
        for (int j = 0; j < 10; j++) atomicAdd(&g_Z[bh * E_ + eg + 16 * j], zs[j]);
    __syncthreads();
    float* s_o = sm;
#pragma unroll
    for (int j = 0; j < 10; j++) {
        s_o[lane * 161 + eg + 16 * j] = l0[j];
        s_o[(lane + 32) * 161 + eg + 16 * j] = l1[j];
    }
    __syncthreads();
    size_t base = ((size_t)bh * N_ + n0) * E_;
#pragma unroll
    for (int i = 0; i < 20; i++) {
        int idx = tid + 512 * i, t = idx / 160, e = idx - t * 160;
        g_logits[base + idx] = s_o[t * 161 + e];
    }
}

// slots: full 160e x 64hd per block, 512-token chunk
__global__ __launch_bounds__(256) void k_slots(const float* __restrict__ x,
                                               const float* __restrict__ s0p) {
    __shared__ float s_p[32 * 162];
    __shared__ float s_x[32 * 68];
    int tid = threadIdx.x, bh = blockIdx.x, nc = blockIdx.y;
    int b = bh / H_, h = bh % H_;
    float inv0 = 1.f / __ldg(s0p);
    int te = tid & 15, th = tid >> 4;
    u64 acc[5][4];
#pragma unroll
    for (int j = 0; j < 5; j++)
#pragma unroll
        for (int c = 0; c < 4; c++) acc[j][c] = 0ull;
    for (int sb = 0; sb < 16; sb++) {
        int nb = nc * 512 + sb * 32;
        __syncthreads();
#pragma unroll
        for (int i = 0; i < 20; i++) {
            int idx = tid + 256 * i;
            int n = idx / 160, e = idx - n * 160;
            s_p[n * 162 + e] = __expf(g_logits[((size_t)bh * N_ + nb + n) * E_ + e] * inv0);
        }
#pragma unroll
        for (int i = 0; i < 8; i++) {
            int idx = tid + 256 * i, n = idx >> 6, d = idx & 63;
            s_x[n * 68 + d] = x[((size_t)(b * N_ + nb + n)) * D_ + h * HD_ + d];
        }
        __syncthreads();
#pragma unroll 2
        for (int n = 0; n < 32; n++) {
            u64 xd[4];
#pragma unroll
            for (int c = 0; c < 4; c++) {
                float xv = s_x[n * 68 + th * 4 + c];
                xd[c] = pack2(xv, xv);
            }
#pragma unroll
            for (int j = 0; j < 5; j++) {
                u64 pv = *(const u64*)(s_p + n * 162 + te * 10 + 2 * j);
#pragma unroll
                for (int c = 0; c < 4; c++) ffma2(acc[j][c], pv, xd[c]);
            }
        }
    }
#pragma unroll
    for (int j = 0; j < 5; j++)
#pragma unroll
        for (int c = 0; c < 4; c++) {
            float lo, hi;
            unpack2(acc[j][c], lo, hi);
            int e = te * 10 + 2 * j, hd = th * 4 + c;
            atomicAdd(&g_slots[((size_t)(b * E_ + e)) * D_ + h * HD_ + hd], lo);
            atomicAdd(&g_slots[((size_t)(b * E_ + e + 1)) * D_ + h * HD_ + hd], hi);
        }
}

// unified MLP layer1 (core + occ): f32x2 m-pairs, Z-divide fused into staging
__global__ __launch_bounds__(128) void k_mlp1u(const float* __restrict__ cw1,
                                               const float* __restrict__ cb1,
                                               const float* __restrict__ ow1,
                                               const float* __restrict__ ob1) {
    __shared__ float s_in[4 * 768];
    int bx = blockIdx.x, tid = threadIdx.x;
    const float *w1, *b1;
    float* o;
    int M, El, e0, e, t;
    if (bx < 192) { e = bx / 6; t = bx % 6; w1 = cw1; b1 = cb1; M = CH_; El = NC_; e0 = 0; o = g_hid; }
    else { int i = bx - 192; e = i >> 1; t = i & 1; w1 = ow1; b1 = ob1; M = OH_; El = NU_; e0 = NC_; o = g_hid2; }
    for (int idx = tid; idx < 4 * 768; idx += 128) {
        int b = idx / 768, d = idx - b * 768;
        float z = g_Z[(b * H_ + (d >> 6)) * E_ + e0 + e];
        s_in[idx] = g_slots[((size_t)(b * E_ + e0 + e)) * D_ + d] / z;
    }
    __syncthreads();
    int m = (t * 128 + tid) * 4;
    if (m >= M) return;
    u64 acc[4][2];
#pragma unroll
    for (int bb = 0; bb < 4; bb++) { acc[bb][0] = 0ull; acc[bb][1] = 0ull; }
    size_t st4 = M >> 2;
    const float4* wp = (const float4*)w1 + (size_t)e * 768 * st4 + (m >> 2);
#pragma unroll 1
    for (int k0 = 0; k0 < 768; k0 += 8) {
        float4 wv[8];
#pragma unroll
        for (int i = 0; i < 8; i++) wv[i] = wp[(size_t)(k0 + i) * st4];
#pragma unroll
        for (int i = 0; i < 8; i++) {
            u64 wlo = pack2(wv[i].x, wv[i].y), whi = pack2(wv[i].z, wv[i].w);
#pragma unroll
            for (int bb = 0; bb < 4; bb++) {
                float sv = s_in[bb * 768 + k0 + i];
                u64 sp = pack2(sv, sv);
                ffma2(acc[bb][0], wlo, sp);
                ffma2(acc[bb][1], whi, sp);
            }
        }
    }
    float4 bv = *(const float4*)(b1 + (size_t)e * M + m);
#pragma unroll
    for (int bb = 0; bb < 4; bb++) {
        float a0, a1, a2, a3;
        unpack2(acc[bb][0], a0, a1);
        unpack2(acc[bb][1], a2, a3);
        float4 r;
        r.x = gelu_exact(a0 + bv.x);
        r.y = gelu_exact(a1 + bv.y);
        r.z = gelu_exact(a2 + bv.z);
        r.w = gelu_exact(a3 + bv.w);
        *(float4*)(o + ((size_t)(bb * El + e)) * M + m) = r;
    }
}

// unified MLP layer2 (core ksplit=4 + occ): f32x2 m-pairs, atomics into g_eo
__global__ __launch_bounds__(128) void k_mlp2u(const float* __restrict__ cw2,
                                               const float* __restrict__ cb2,
                                               const float* __restrict__ ow2,
                                               const float* __restrict__ ob2) {
    __shared__ float s_h[4 * 768];
    int bx = blockIdx.x, tid = threadIdx.x;
    const float *w2, *b2, *hid;
    int K, El, e0, e, t, ks;
    if (bx < 256) { e = bx >> 3; t = (bx >> 2) & 1; ks = bx & 3; w2 = cw2; b2 = cb2; K = CH_; El = NC_; e0 = 0; hid = g_hid; }
    else { int i = bx - 256; e = i >> 1; t = i & 1; ks = 0; w2 = ow2; b2 = ob2; K = OH_; El = NU_; e0 = NC_; hid = g_hid2; }
    for (int idx = tid; idx < 4 * 768; idx += 128) {
        int b = idx / 768, d = idx - b * 768;
        s_h[idx] = hid[((size_t)(b * El + e)) * K + ks * 768 + d];
    }
    __syncthreads();
    int m = (t * 128 + tid) * 4;
    if (m >= 768) return;
    u64 acc[4][2];
    float4 bv = make_float4(0.f, 0.f, 0.f, 0.f);
    if (ks == 0) bv = *(const float4*)(b2 + (size_t)e * 768 + m);
#pragma unroll
    for (int bb = 0; bb < 4; bb++) {
        acc[bb][0] = pack2(bv.x, bv.y);
        acc[bb][1] = pack2(bv.z, bv.w);
    }
    const float4* wp = (const float4*)w2 + ((size_t)e * K + ks * 768) * 192 + (m >> 2);
#pragma unroll 1
    for (int k0 = 0; k0 < 768; k0 += 8) {
        float4 wv[8];
#pragma unroll
        for (int i = 0; i < 8; i++) wv[i] = wp[(size_t)(k0 + i) * 192];
#pragma unroll
        for (int i = 0; i < 8; i++) {
            u64 wlo = pack2(wv[i].x, wv[i].y), whi = pack2(wv[i].z, wv[i].w);
#pragma unroll
            for (int bb = 0; bb < 4; bb++) {
                float sv = s_h[bb * 768 + k0 + i];
                u64 sp = pack2(sv, sv);
                ffma2(acc[bb][0], wlo, sp);
                ffma2(acc[bb][1], whi, sp);
            }
        }
    }
#pragma unroll
    for (int bb = 0; bb < 4; bb++) {
        float a0, a1, a2, a3;
        unpack2(acc[bb][0], a0, a1);
        unpack2(acc[bb][1], a2, a3);
        float* dst = &g_eo[((size_t)(bb * E_ + e0 + e)) * D_ + m];
        atomicAdd(dst + 0, a0);
        atomicAdd(dst + 1, a1);
        atomicAdd(dst + 2, a2);
        atomicAdd(dst + 3, a3);
    }
}

__global__ __launch_bounds__(256) void k_combine(float* __restrict__ out,
                                                 const float* __restrict__ s1p) {
    extern __shared__ float sm[];
    float* s_eoT = sm;
    float* s_w = sm + 64 * 162;
    int tid = threadIdx.x, lane = tid & 31, wid = tid >> 5;
    int n0 = blockIdx.x * 64, bh = blockIdx.y, b = bh / H_, h = bh % H_;
#pragma unroll
    for (int i = 0; i < 40; i++) {
        int idx = tid + 256 * i, e = idx >> 6, hd = idx & 63;
        s_eoT[hd * 162 + e] = g_eo[((size_t)(b * E_ + e)) * D_ + h * HD_ + hd];
    }
    float inv1 = 1.f / __ldg(s1p);
    for (int i = 0; i < 8; i++) {
        int t = wid * 8 + i;
        const float* lp = g_logits + ((size_t)bh * N_ + n0 + t) * E_;
        float v[5];
#pragma unroll
        for (int j = 0; j < 5; j++) v[j] = lp[lane + 32 * j] * inv1;
        float mx = fmaxf(fmaxf(fmaxf(v[0], v[1]), fmaxf(v[2], v[3])), v[4]);
#pragma unroll
        for (int o = 16; o; o >>= 1) mx = fmaxf(mx, __shfl_xor_sync(~0u, mx, o));
#pragma unroll
        for (int j = 0; j < 5; j++) v[j] = (v[j] - mx) * 0.5f;
        float tau = -1.f;
        for (int it = 0; it < 30; it++) {
            float s1 = 0.f, s2 = 0.f;
#pragma unroll
            for (int j = 0; j < 5; j++) {
                float d = fmaxf(v[j] - tau, 0.f);
                s1 += d;
                s2 = fmaf(d, d, s2);
            }
#pragma unroll
            for (int o = 16; o; o >>= 1) {
                s1 += __shfl_xor_sync(~0u, s1, o);
                s2 += __shfl_xor_sync(~0u, s2, o);
            }
            float dt = (s2 - 1.f) / (2.f * s1);
            tau += dt;
            if (dt < 1e-7f) break;
        }
#pragma unroll
        for (int j = 0; j < 5; j++) {
            float d = fmaxf(v[j] - tau, 0.f);
            s_w[t * 160 + lane + 32 * j] = d * d;
        }
    }
    __syncthreads();
    int hq = tid & 15, tq = tid >> 4;
    u64 acc[4][4];
#pragma unroll
    for (int tt = 0; tt < 4; tt++)
#pragma unroll
        for (int c = 0; c < 4; c++) acc[tt][c] = 0ull;
#pragma unroll 2
    for (int ep = 0; ep < 80; ep++) {
        u64 wv[4], ev[4];
#pragma unroll
        for (int tt = 0; tt < 4; tt++) wv[tt] = *(const u64*)(s_w + (tq * 4 + tt) * 160 + 2 * ep);
#pragma unroll
        for (int c = 0; c < 4; c++) ev[c] = *(const u64*)(s_eoT + (hq * 4 + c) * 162 + 2 * ep);
#pragma unroll
        for (int tt = 0; tt < 4; tt++)
#pragma unroll
            for (int c = 0; c < 4; c++) ffma2(acc[tt][c], wv[tt], ev[c]);
    }
#pragma unroll
    for (int tt = 0; tt < 4; tt++) {
        float4 r = make_float4(sum2(acc[tt][0]), sum2(acc[tt][1]),
                               sum2(acc[tt][2]), sum2(acc[tt][3]));
        *(float4*)(out + ((size_t)(b * N_ + n0 + tq * 4 + tt)) * D_ + h * HD_ + hq * 4) = r;
    }
}

extern "C" void kernel_launch(void* const* d_in, const int* in_sizes, int n_in,
                              void* d_out, int out_size) {
    const float* x   = (const float*)d_in[0];
    const float* phi = (const float*)d_in[1];
    const float* kgm = (const float*)d_in[2];
    const float* kbt = (const float*)d_in[3];
    const float* qgm = (const float*)d_in[4];
    const float* qbt = (const float*)d_in[5];
    const float* lnw = (const float*)d_in[6];
    const float* lnb = (const float*)d_in[7];
    const float* s0  = (const float*)d_in[8];
    const float* s1  = (const float*)d_in[9];
    const float* cw1 = (const float*)d_in[10];
    const float* cb1 = (const float*)d_in[11];
    const float* cw2 = (const float*)d_in[12];
    const float* cb2 = (const float*)d_in[13];
    const float* ow1 = (const float*)d_in[14];
    const float* ob1 = (const float*)d_in[15];
    const float* ow2 = (const float*)d_in[16];
    const float* ob2 = (const float*)d_in[17];
    float* out = (float*)d_out;

    const int SM_LOG = (64 * 66 + 160 * 66 + 64) * 4;
    const int SM_CMB = (64 * 162 + 64 * 160) * 4;
    cudaFuncSetAttribute(k_logits, cudaFuncAttributeMaxDynamicSharedMemorySize, SM_LOG);
    cudaFuncSetAttribute(k_combine, cudaFuncAttributeMaxDynamicSharedMemorySize, SM_CMB);

    k_zero<<<1920, 256>>>();
    k_prep_q<<<60, 1024>>>(phi, qgm, qbt, lnw, lnb);
    k_logits<<<dim3(64, 48), 512, SM_LOG>>>(x, kgm, kbt, s0);
    k_slots<<<dim3(48, 8), 256>>>(x, s0);
    k_mlp1u<<<448, 128>>>(cw1, cb1, ow1, ob1);
    k_mlp2u<<<512, 128>>>(cw2, cb2, ow2, ob2);
    k_combine<<<dim3(64, 48), 256, SM_CMB>>>(out, s1);
}

// round 13
// speedup vs baseline: 1.4751x; 1.1123x over previous
#include <cuda_runtime.h>
#include <math.h>

#define B_ 4
#define N_ 4096
#define D_ 768
#define H_ 12
#define HD_ 64
#define E_ 160
#define NC_ 32
#define NU_ 128
#define CH_ 3072
#define OH_ 768
#define BH_ 48

typedef unsigned long long u64;
typedef unsigned int u32;

__device__ float g_qn[H_ * E_ * HD_];
__device__ float g_logits[(size_t)BH_ * N_ * E_];
__device__ float g_Z[BH_ * E_];
__device__ float g_slots[B_ * E_ * D_];
__device__ float g_hid[B_ * NC_ * CH_];
__device__ float g_hid2[B_ * NU_ * OH_];
__device__ float g_eo[B_ * E_ * D_];

__device__ __forceinline__ void ffma2(u64 &a, u64 x, u64 y) {
    asm("fma.rn.f32x2 %0, %1, %2, %0;" : "+l"(a) : "l"(x), "l"(y));
}
__device__ __forceinline__ u64 pack2(float lo, float hi) {
    u64 r;
    asm("mov.b64 %0, {%1,%2};" : "=l"(r) : "f"(lo), "f"(hi));
    return r;
}
__device__ __forceinline__ void unpack2(u64 v, float &lo, float &hi) {
    asm("mov.b64 {%0,%1}, %2;" : "=f"(lo), "=f"(hi) : "l"(v));
}
__device__ __forceinline__ float sum2(u64 v) {
    float lo, hi; unpack2(v, lo, hi); return lo + hi;
}
__device__ __forceinline__ float gelu_exact(float v) {
    return 0.5f * v * (1.0f + erff(v * 0.70710678f));
}
__device__ __forceinline__ float tf32r(float f) {
    u32 r;
    asm("cvt.rna.tf32.f32 %0, %1;" : "=r"(r) : "f"(f));
    return __uint_as_float(r);
}
__device__ __forceinline__ void mma_tf32(float* c, u32 a0, u32 a1, u32 a2, u32 a3,
                                         u32 b0, u32 b1) {
    asm("mma.sync.aligned.m16n8k8.row.col.f32.tf32.tf32.f32 "
        "{%0,%1,%2,%3},{%4,%5,%6,%7},{%8,%9},{%0,%1,%2,%3};"
        : "+f"(c[0]), "+f"(c[1]), "+f"(c[2]), "+f"(c[3])
        : "r"(a0), "r"(a1), "r"(a2), "r"(a3), "r"(b0), "r"(b1));
}

__global__ void k_zero() {
    int i = blockIdx.x * 256 + threadIdx.x;
    if (i < B_ * E_ * D_) { g_slots[i] = 0.f; g_eo[i] = 0.f; }
    if (i < BH_ * E_) g_Z[i] = 0.f;
}

__global__ void k_prep_q(const float* __restrict__ phi, const float* __restrict__ qg,
                         const float* __restrict__ qb, const float* __restrict__ lw,
                         const float* __restrict__ lb) {
    int gw = (blockIdx.x * blockDim.x + threadIdx.x) >> 5, lane = threadIdx.x & 31;
    if (gw >= H_ * E_) return;
    int h = gw / E_, e = gw % E_, d0 = lane, d1 = lane + 32;
    float t0 = phi[(size_t)e * D_ + h * HD_ + d0] * qg[d0] + qb[d0];
    float t1 = phi[(size_t)e * D_ + h * HD_ + d1] * qg[d1] + qb[d1];
    float s = t0 + t1;
#pragma unroll
    for (int o = 16; o; o >>= 1) s += __shfl_xor_sync(~0u, s, o);
    float m = s * (1.f / 64.f), c0 = t0 - m, c1 = t1 - m, v = c0 * c0 + c1 * c1;
#pragma unroll
    for (int o = 16; o; o >>= 1) v += __shfl_xor_sync(~0u, v, o);
    float inv = rsqrtf(v * (1.f / 64.f) + 1e-5f);
    float y0 = c0 * inv * lw[d0] + lb[d0], y1 = c1 * inv * lw[d1] + lb[d1];
    float ss = y0 * y0 + y1 * y1;
#pragma unroll
    for (int o = 16; o; o >>= 1) ss += __shfl_xor_sync(~0u, ss, o);
    float r = 1.f / (sqrtf(ss) + 1e-6f);
    g_qn[gw * HD_ + d0] = y0 * r;
    g_qn[gw * HD_ + d1] = y1 * r;
}

// logits via tf32 mma: per block (64 tokens x 160 experts x 64d)
__global__ __launch_bounds__(512) void k_logits(const float* __restrict__ x,
                                                const float* __restrict__ kg,
                                                const float* __restrict__ kb,
                                                const float* __restrict__ s0p) {
    extern __shared__ float sm[];
    float* s_k = sm;                 // [64][66]
    float* s_q = sm + 64 * 66;       // [160][66]
    float* s_inv = s_q + 160 * 66;   // [64]
    int tid = threadIdx.x, n0 = blockIdx.x * 64, bh = blockIdx.y;
    int b = bh / H_, h = bh % H_;
#pragma unroll
    for (int i = 0; i < 8; i++) {
        int idx = tid + 512 * i, t = idx >> 6, d = idx & 63;
        s_k[t * 66 + d] = x[((size_t)(b * N_ + n0 + t)) * D_ + h * HD_ + d] * kg[d] + kb[d];
    }
#pragma unroll
    for (int i = 0; i < 20; i++) {
        int idx = tid + 512 * i, e = idx >> 6, d = idx & 63;
        s_q[e * 66 + d] = tf32r(g_qn[(h * E_ + e) * HD_ + d]);
    }
    __syncthreads();
    if (tid < 64) {
        float ss = 0.f;
#pragma unroll
        for (int d = 0; d < 64; d++) { float v = s_k[tid * 66 + d]; ss += v * v; }
        s_inv[tid] = 1.f / (sqrtf(ss) + 1e-6f);
    }
    __syncthreads();
#pragma unroll
    for (int i = 0; i < 8; i++) {
        int idx = tid + 512 * i, t = idx >> 6, d = idx & 63;
        s_k[t * 66 + d] = tf32r(s_k[t * 66 + d] * s_inv[t]);
    }
    __syncthreads();

    int w = tid >> 5, gid = (tid & 31) >> 2, tig = tid & 3;
    int mt = w & 3, nt0 = (w >> 2) * 5;
    float c[5][4];
#pragma unroll
    for (int j = 0; j < 5; j++)
#pragma unroll
        for (int q = 0; q < 4; q++) c[j][q] = 0.f;
#pragma unroll
    for (int ks = 0; ks < 8; ks++) {
        int k0 = ks * 8;
        u32 a0 = __float_as_uint(s_k[(mt * 16 + gid) * 66 + k0 + tig]);
        u32 a1 = __float_as_uint(s_k[(mt * 16 + gid + 8) * 66 + k0 + tig]);
        u32 a2 = __float_as_uint(s_k[(mt * 16 + gid) * 66 + k0 + tig + 4]);
        u32 a3 = __float_as_uint(s_k[(mt * 16 + gid + 8) * 66 + k0 + tig + 4]);
#pragma unroll
        for (int j = 0; j < 5; j++) {
            int e0 = (nt0 + j) * 8;
            u32 b0 = __float_as_uint(s_q[(e0 + gid) * 66 + k0 + tig]);
            u32 b1 = __float_as_uint(s_q[(e0 + gid) * 66 + k0 + tig + 4]);
            mma_tf32(c[j], a0, a1, a2, a3, b0, b1);
        }
    }
    __syncthreads();
    float* s_o = sm;                 // [64][161] (reuse)
#pragma unroll
    for (int j = 0; j < 5; j++) {
        int e = (nt0 + j) * 8 + 2 * tig;
        s_o[(mt * 16 + gid) * 161 + e] = c[j][0];
        s_o[(mt * 16 + gid) * 161 + e + 1] = c[j][1];
        s_o[(mt * 16 + gid + 8) * 161 + e] = c[j][2];
        s_o[(mt * 16 + gid + 8) * 161 + e + 1] = c[j][3];
    }
    __syncthreads();
    float inv0 = 1.f / __ldg(s0p);
    if (tid < 160) {
        float zsum = 0.f;
#pragma unroll 8
        for (int t = 0; t < 64; t++) zsum += __expf(s_o[t * 161 + tid] * inv0);
        atomicAdd(&g_Z[bh * E_ + tid], zsum);
    }
    size_t base = ((size_t)bh * N_ + n0) * E_;
#pragma unroll
    for (int i = 0; i < 20; i++) {
        int idx = tid + 512 * i, t = idx / 160, e = idx - t * 160;
        g_logits[base + idx] = s_o[t * 161 + e];
    }
}

// slots via tf32 mma: per block full 160e x 64hd, 512-token chunk
__global__ __launch_bounds__(256) void k_slots(const float* __restrict__ x,
                                               const float* __restrict__ s0p) {
    __shared__ float s_p[160 * 34];   // [e][n] tf32-rounded probs
    __shared__ float s_x[32 * 68];    // [n][hd]
    int tid = threadIdx.x, bh = blockIdx.x, nc = blockIdx.y;
    int b = bh / H_, h = bh % H_;
    float inv0 = 1.f / __ldg(s0p);
    int w = tid >> 5, gid = (tid & 31) >> 2, tig = tid & 3;
    int hd0 = w * 8;
    float c[10][4];
#pragma unroll
    for (int mtt = 0; mtt < 10; mtt++)
#pragma unroll
        for (int q = 0; q < 4; q++) c[mtt][q] = 0.f;
    for (int sb = 0; sb < 16; sb++) {
        int nb = nc * 512 + sb * 32;
        __syncthreads();
#pragma unroll
        for (int i = 0; i < 20; i++) {
            int idx = tid + 256 * i;
            int n = idx / 160, e = idx - n * 160;
            float l = g_logits[((size_t)bh * N_ + nb + n) * E_ + e];
            s_p[e * 34 + n] = tf32r(__expf(l * inv0));
        }
#pragma unroll
        for (int i = 0; i < 8; i++) {
            int idx = tid + 256 * i, n = idx >> 6, d = idx & 63;
            s_x[n * 68 + d] = tf32r(x[((size_t)(b * N_ + nb + n)) * D_ + h * HD_ + d]);
        }
        __syncthreads();
#pragma unroll
        for (int ks = 0; ks < 4; ks++) {
            int k0 = ks * 8;
            u32 b0 = __float_as_uint(s_x[(k0 + tig) * 68 + hd0 + gid]);
            u32 b1 = __float_as_uint(s_x[(k0 + tig + 4) * 68 + hd0 + gid]);
#pragma unroll
            for (int mtt = 0; mtt < 10; mtt++) {
                u32 a0 = __float_as_uint(s_p[(mtt * 16 + gid) * 34 + k0 + tig]);
                u32 a1 = __float_as_uint(s_p[(mtt * 16 + gid + 8) * 34 + k0 + tig]);
                u32 a2 = __float_as_uint(s_p[(mtt * 16 + gid) * 34 + k0 + tig + 4]);
                u32 a3 = __float_as_uint(s_p[(mtt * 16 + gid + 8) * 34 + k0 + tig + 4]);
                mma_tf32(c[mtt], a0, a1, a2, a3, b0, b1);
            }
        }
    }
#pragma unroll
    for (int mtt = 0; mtt < 10; mtt++) {
        int e0 = mtt * 16 + gid, hd = hd0 + 2 * tig;
        atomicAdd(&g_slots[((size_t)(b * E_ + e0)) * D_ + h * HD_ + hd], c[mtt][0]);
        atomicAdd(&g_slots[((size_t)(b * E_ + e0)) * D_ + h * HD_ + hd + 1], c[mtt][1]);
        atomicAdd(&g_slots[((size_t)(b * E_ + e0 + 8)) * D_ + h * HD_ + hd], c[mtt][2]);
        atomicAdd(&g_slots[((size_t)(b * E_ + e0 + 8)) * D_ + h * HD_ + hd + 1], c[mtt][3]);
    }
}

// unified MLP layer1 (core + occ): f32x2 m-pairs, Z-divide fused into staging
__global__ __launch_bounds__(128) void k_mlp1u(const float* __restrict__ cw1,
                                               const float* __restrict__ cb1,
                                               const float* __restrict__ ow1,
                                               const float* __restrict__ ob1) {
    __shared__ float s_in[4 * 768];
    int bx = blockIdx.x, tid = threadIdx.x;
    const float *w1, *b1;
    float* o;
    int M, El, e0, e, t;
    if (bx < 192) { e = bx / 6; t = bx % 6; w1 = cw1; b1 = cb1; M = CH_; El = NC_; e0 = 0; o = g_hid; }
    else { int i = bx - 192; e = i >> 1; t = i & 1; w1 = ow1; b1 = ob1; M = OH_; El = NU_; e0 = NC_; o = g_hid2; }
    for (int idx = tid; idx < 4 * 768; idx += 128) {
        int b = idx / 768, d = idx - b * 768;
        float z = g_Z[(b * H_ + (d >> 6)) * E_ + e0 + e];
        s_in[idx] = g_slots[((size_t)(b * E_ + e0 + e)) * D_ + d] / z;
    }
    __syncthreads();
    int m = (t * 128 + tid) * 4;
    if (m >= M) return;
    u64 acc[4][2];
#pragma unroll
    for (int bb = 0; bb < 4; bb++) { acc[bb][0] = 0ull; acc[bb][1] = 0ull; }
    size_t st4 = M >> 2;
    const float4* wp = (const float4*)w1 + (size_t)e * 768 * st4 + (m >> 2);
#pragma unroll 1
    for (int k0 = 0; k0 < 768; k0 += 8) {
        float4 wv[8];
#pragma unroll
        for (int i = 0; i < 8; i++) wv[i] = wp[(size_t)(k0 + i) * st4];
#pragma unroll
        for (int i = 0; i < 8; i++) {
            u64 wlo = pack2(wv[i].x, wv[i].y), whi = pack2(wv[i].z, wv[i].w);
#pragma unroll
            for (int bb = 0; bb < 4; bb++) {
                float sv = s_in[bb * 768 + k0 + i];
                u64 sp = pack2(sv, sv);
                ffma2(acc[bb][0], wlo, sp);
                ffma2(acc[bb][1], whi, sp);
            }
        }
    }
    float4 bv = *(const float4*)(b1 + (size_t)e * M + m);
#pragma unroll
    for (int bb = 0; bb < 4; bb++) {
        float a0, a1, a2, a3;
        unpack2(acc[bb][0], a0, a1);
        unpack2(acc[bb][1], a2, a3);
        float4 r;
        r.x = gelu_exact(a0 + bv.x);
        r.y = gelu_exact(a1 + bv.y);
        r.z = gelu_exact(a2 + bv.z);
        r.w = gelu_exact(a3 + bv.w);
        *(float4*)(o + ((size_t)(bb * El + e)) * M + m) = r;
    }
}

// unified MLP layer2 (core ksplit=4 + occ): f32x2 m-pairs, atomics into g_eo
__global__ __launch_bounds__(128) void k_mlp2u(const float* __restrict__ cw2,
                                               const float* __restrict__ cb2,
                                               const float* __restrict__ ow2,
                                               const float* __restrict__ ob2) {
    __shared__ float s_h[4 * 768];
    int bx = blockIdx.x, tid = threadIdx.x;
    const float *w2, *b2, *hid;
    int K, El, e0, e, t, ks;
    if (bx < 256) { e = bx >> 3; t = (bx >> 2) & 1; ks = bx & 3; w2 = cw2; b2 = cb2; K = CH_; El = NC_; e0 = 0; hid = g_hid; }
    else { int i = bx - 256; e = i >> 1; t = i & 1; ks = 0; w2 = ow2; b2 = ob2; K = OH_; El = NU_; e0 = NC_; hid = g_hid2; }
    for (int idx = tid; idx < 4 * 768; idx += 128) {
        int b = idx / 768, d = idx - b * 768;
        s_h[idx] = hid[((size_t)(b * El + e)) * K + ks * 768 + d];
    }
    __syncthreads();
    int m = (t * 128 + tid) * 4;
    if (m >= 768) return;
    u64 acc[4][2];
    float4 bv = make_float4(0.f, 0.f, 0.f, 0.f);
    if (ks == 0) bv = *(const float4*)(b2 + (size_t)e * 768 + m);
#pragma unroll
    for (int bb = 0; bb < 4; bb++) {
        acc[bb][0] = pack2(bv.x, bv.y);
        acc[bb][1] = pack2(bv.z, bv.w);
    }
    const float4* wp = (const float4*)w2 + ((size_t)e * K + ks * 768) * 192 + (m >> 2);
#pragma unroll 1
    for (int k0 = 0; k0 < 768; k0 += 8) {
        float4 wv[8];
#pragma unroll
        for (int i = 0; i < 8; i++) wv[i] = wp[(size_t)(k0 + i) * 192];
#pragma unroll
        for (int i = 0; i < 8; i++) {
            u64 wlo = pack2(wv[i].x, wv[i].y), whi = pack2(wv[i].z, wv[i].w);
#pragma unroll
            for (int bb = 0; bb < 4; bb++) {
                float sv = s_h[bb * 768 + k0 + i];
                u64 sp = pack2(sv, sv);
                ffma2(acc[bb][0], wlo, sp);
                ffma2(acc[bb][1], whi, sp);
            }
        }
    }
#pragma unroll
    for (int bb = 0; bb < 4; bb++) {
        float a0, a1, a2, a3;
        unpack2(acc[bb][0], a0, a1);
        unpack2(acc[bb][1], a2, a3);
        float* dst = &g_eo[((size_t)(bb * E_ + e0 + e)) * D_ + m];
        atomicAdd(dst + 0, a0);
        atomicAdd(dst + 1, a1);
        atomicAdd(dst + 2, a2);
        atomicAdd(dst + 3, a3);
    }
}

__global__ __launch_bounds__(256) void k_combine(float* __restrict__ out,
                                                 const float* __restrict__ s1p) {
    extern __shared__ float sm[];
    float* s_eoT = sm;
    float* s_w = sm + 64 * 162;
    int tid = threadIdx.x, lane = tid & 31, wid = tid >> 5;
    int n0 = blockIdx.x * 64, bh = blockIdx.y, b = bh / H_, h = bh % H_;
#pragma unroll
    for (int i = 0; i < 40; i++) {
        int idx = tid + 256 * i, e = idx >> 6, hd = idx & 63;
        s_eoT[hd * 162 + e] = g_eo[((size_t)(b * E_ + e)) * D_ + h * HD_ + hd];
    }
    float inv1 = 1.f / __ldg(s1p);
    for (int i = 0; i < 8; i++) {
        int t = wid * 8 + i;
        const float* lp = g_logits + ((size_t)bh * N_ + n0 + t) * E_;
        float v[5];
#pragma unroll
        for (int j = 0; j < 5; j++) v[j] = lp[lane + 32 * j] * inv1;
        float mx = fmaxf(fmaxf(fmaxf(v[0], v[1]), fmaxf(v[2], v[3])), v[4]);
#pragma unroll
        for (int o = 16; o; o >>= 1) mx = fmaxf(mx, __shfl_xor_sync(~0u, mx, o));
#pragma unroll
        for (int j = 0; j < 5; j++) v[j] = (v[j] - mx) * 0.5f;
        float tau = -1.f;
        for (int it = 0; it < 30; it++) {
            float s1 = 0.f, s2 = 0.f;
#pragma unroll
            for (int j = 0; j < 5; j++) {
                float d = fmaxf(v[j] - tau, 0.f);
                s1 += d;
                s2 = fmaf(d, d, s2);
            }
#pragma unroll
            for (int o = 16; o; o >>= 1) {
                s1 += __shfl_xor_sync(~0u, s1, o);
                s2 += __shfl_xor_sync(~0u, s2, o);
            }
            float dt = (s2 - 1.f) / (2.f * s1);
            tau += dt;
            if (dt < 1e-7f) break;
        }
#pragma unroll
        for (int j = 0; j < 5; j++) {
            float d = fmaxf(v[j] - tau, 0.f);
            s_w[t * 160 + lane + 32 * j] = d * d;
        }
    }
    __syncthreads();
    int hq = tid & 15, tq = tid >> 4;
    u64 acc[4][4];
#pragma unroll
    for (int tt = 0; tt < 4; tt++)
#pragma unroll
        for (int c = 0; c < 4; c++) acc[tt][c] = 0ull;
#pragma unroll 2
    for (int ep = 0; ep < 80; ep++) {
        u64 wv[4], ev[4];
#pragma unroll
        for (int tt = 0; tt < 4; tt++) wv[tt] = *(const u64*)(s_w + (tq * 4 + tt) * 160 + 2 * ep);
#pragma unroll
        for (int c = 0; c < 4; c++) ev[c] = *(const u64*)(s_eoT + (hq * 4 + c) * 162 + 2 * ep);
#pragma unroll
        for (int tt = 0; tt < 4; tt++)
#pragma unroll
            for (int c = 0; c < 4; c++) ffma2(acc[tt][c], wv[tt], ev[c]);
    }
#pragma unroll
    for (int tt = 0; tt < 4; tt++) {
        float4 r = make_float4(sum2(acc[tt][0]), sum2(acc[tt][1]),
                               sum2(acc[tt][2]), sum2(acc[tt][3]));
        *(float4*)(out + ((size_t)(b * N_ + n0 + tq * 4 + tt)) * D_ + h * HD_ + hq * 4) = r;
    }
}

extern "C" void kernel_launch(void* const* d_in, const int* in_sizes, int n_in,
                              void* d_out, int out_size) {
    const float* x   = (const float*)d_in[0];
    const float* phi = (const float*)d_in[1];
    const float* kgm = (const float*)d_in[2];
    const float* kbt = (const float*)d_in[3];
    const float* qgm = (const float*)d_in[4];
    const float* qbt = (const float*)d_in[5];
    const float* lnw = (const float*)d_in[6];
    const float* lnb = (const float*)d_in[7];
    const float* s0  = (const float*)d_in[8];
    const float* s1  = (const float*)d_in[9];
    const float* cw1 = (const float*)d_in[10];
    const float* cb1 = (const float*)d_in[11];
    const float* cw2 = (const float*)d_in[12];
    const float* cb2 = (const float*)d_in[13];
    const float* ow1 = (const float*)d_in[14];
    const float* ob1 = (const float*)d_in[15];
    const float* ow2 = (const float*)d_in[16];
    const float* ob2 = (const float*)d_in[17];
    float* out = (float*)d_out;

    const int SM_LOG = (64 * 66 + 160 * 66 + 64) * 4;
    const int SM_CMB = (64 * 162 + 64 * 160) * 4;
    cudaFuncSetAttribute(k_logits, cudaFuncAttributeMaxDynamicSharedMemorySize, SM_LOG);
    cudaFuncSetAttribute(k_combine, cudaFuncAttributeMaxDynamicSharedMemorySize, SM_CMB);

    k_zero<<<1920, 256>>>();
    k_prep_q<<<60, 1024>>>(phi, qgm, qbt, lnw, lnb);
    k_logits<<<dim3(64, 48), 512, SM_LOG>>>(x, kgm, kbt, s0);
    k_slots<<<dim3(48, 8), 256>>>(x, s0);
    k_mlp1u<<<448, 128>>>(cw1, cb1, ow1, ob1);
    k_mlp2u<<<512, 128>>>(cw2, cb2, ow2, ob2);
    k_combine<<<dim3(64, 48), 256, SM_CMB>>>(out, s1);
}

// round 17
// speedup vs baseline: 1.6692x; 1.1316x over previous
#include <cuda_runtime.h>
#include <math.h>

#define B_ 4
#define N_ 4096
#define D_ 768
#define H_ 12
#define HD_ 64
#define E_ 160
#define NC_ 32
#define NU_ 128
#define CH_ 3072
#define OH_ 768
#define BH_ 48

typedef unsigned long long u64;
typedef unsigned int u32;

__device__ float g_qn[H_ * E_ * HD_];
__device__ float g_logits[(size_t)BH_ * N_ * E_];
__device__ float g_Z[BH_ * E_];
__device__ float g_slots[B_ * E_ * D_];
__device__ float g_hid[B_ * NC_ * CH_];
__device__ float g_hid2[B_ * NU_ * OH_];
__device__ float g_eo[B_ * E_ * D_];

__device__ __forceinline__ void ffma2(u64 &a, u64 x, u64 y) {
    asm("fma.rn.f32x2 %0, %1, %2, %0;" : "+l"(a) : "l"(x), "l"(y));
}
__device__ __forceinline__ u64 pack2(float lo, float hi) {
    u64 r;
    asm("mov.b64 %0, {%1,%2};" : "=l"(r) : "f"(lo), "f"(hi));
    return r;
}
__device__ __forceinline__ void unpack2(u64 v, float &lo, float &hi) {
    asm("mov.b64 {%0,%1}, %2;" : "=f"(lo), "=f"(hi) : "l"(v));
}
__device__ __forceinline__ float sum2(u64 v) {
    float lo, hi; unpack2(v, lo, hi); return lo + hi;
}
__device__ __forceinline__ float gelu_exact(float v) {
    return 0.5f * v * (1.0f + erff(v * 0.70710678f));
}
__device__ __forceinline__ float tf32r(float f) {
    u32 r;
    asm("cvt.rna.tf32.f32 %0, %1;" : "=r"(r) : "f"(f));
    return __uint_as_float(r);
}
__device__ __forceinline__ void mma_tf32(float* c, u32 a0, u32 a1, u32 a2, u32 a3,
                                         u32 b0, u32 b1) {
    asm("mma.sync.aligned.m16n8k8.row.col.f32.tf32.tf32.f32 "
        "{%0,%1,%2,%3},{%4,%5,%6,%7},{%8,%9},{%0,%1,%2,%3};"
        : "+f"(c[0]), "+f"(c[1]), "+f"(c[2]), "+f"(c[3])
        : "r"(a0), "r"(a1), "r"(a2), "r"(a3), "r"(b0), "r"(b1));
}

__global__ void k_zero() {
    int i = blockIdx.x * 256 + threadIdx.x;
    if (i < B_ * E_ * D_) { g_slots[i] = 0.f; g_eo[i] = 0.f; }
    if (i < BH_ * E_) g_Z[i] = 0.f;
}

__global__ void k_prep_q(const float* __restrict__ phi, const float* __restrict__ qg,
                         const float* __restrict__ qb, const float* __restrict__ lw,
                         const float* __restrict__ lb) {
    int gw = (blockIdx.x * blockDim.x + threadIdx.x) >> 5, lane = threadIdx.x & 31;
    if (gw >= H_ * E_) return;
    int h = gw / E_, e = gw % E_, d0 = lane, d1 = lane + 32;
    float t0 = phi[(size_t)e * D_ + h * HD_ + d0] * qg[d0] + qb[d0];
    float t1 = phi[(size_t)e * D_ + h * HD_ + d1] * qg[d1] + qb[d1];
    float s = t0 + t1;
#pragma unroll
    for (int o = 16; o; o >>= 1) s += __shfl_xor_sync(~0u, s, o);
    float m = s * (1.f / 64.f), c0 = t0 - m, c1 = t1 - m, v = c0 * c0 + c1 * c1;
#pragma unroll
    for (int o = 16; o; o >>= 1) v += __shfl_xor_sync(~0u, v, o);
    float inv = rsqrtf(v * (1.f / 64.f) + 1e-5f);
    float y0 = c0 * inv * lw[d0] + lb[d0], y1 = c1 * inv * lw[d1] + lb[d1];
    float ss = y0 * y0 + y1 * y1;
#pragma unroll
    for (int o = 16; o; o >>= 1) ss += __shfl_xor_sync(~0u, ss, o);
    float r = 1.f / (sqrtf(ss) + 1e-6f);
    g_qn[gw * HD_ + d0] = y0 * r;
    g_qn[gw * HD_ + d1] = y1 * r;
}

// logits via tf32 mma: per block (64 tokens x 160 experts x 64d)
__global__ __launch_bounds__(512) void k_logits(const float* __restrict__ x,
                                                const float* __restrict__ kg,
                                                const float* __restrict__ kb,
                                                const float* __restrict__ s0p) {
    extern __shared__ float sm[];
    float* s_k = sm;                 // [64][66]
    float* s_q = sm + 64 * 66;       // [160][66]
    float* s_inv = s_q + 160 * 66;   // [64]
    int tid = threadIdx.x, n0 = blockIdx.x * 64, bh = blockIdx.y;
    int b = bh / H_, h = bh % H_;
#pragma unroll
    for (int i = 0; i < 8; i++) {
        int idx = tid + 512 * i, t = idx >> 6, d = idx & 63;
        s_k[t * 66 + d] = x[((size_t)(b * N_ + n0 + t)) * D_ + h * HD_ + d] * kg[d] + kb[d];
    }
#pragma unroll
    for (int i = 0; i < 20; i++) {
        int idx = tid + 512 * i, e = idx >> 6, d = idx & 63;
        s_q[e * 66 + d] = tf32r(g_qn[(h * E_ + e) * HD_ + d]);
    }
    __syncthreads();
    if (tid < 64) {
        float ss = 0.f;
#pragma unroll
        for (int d = 0; d < 64; d++) { float v = s_k[tid * 66 + d]; ss += v * v; }
        s_inv[tid] = 1.f / (sqrtf(ss) + 1e-6f);
    }
    __syncthreads();
#pragma unroll
    for (int i = 0; i < 8; i++) {
        int idx = tid + 512 * i, t = idx >> 6, d = idx & 63;
        s_k[t * 66 + d] = tf32r(s_k[t * 66 + d] * s_inv[t]);
    }
    __syncthreads();

    int w = tid >> 5, gid = (tid & 31) >> 2, tig = tid & 3;
    int mt = w & 3, nt0 = (w >> 2) * 5;
    float c[5][4];
#pragma unroll
    for (int j = 0; j < 5; j++)
#pragma unroll
        for (int q = 0; q < 4; q++) c[j][q] = 0.f;
#pragma unroll
    for (int ks = 0; ks < 8; ks++) {
        int k0 = ks * 8;
        u32 a0 = __float_as_uint(s_k[(mt * 16 + gid) * 66 + k0 + tig]);
        u32 a1 = __float_as_uint(s_k[(mt * 16 + gid + 8) * 66 + k0 + tig]);
        u32 a2 = __float_as_uint(s_k[(mt * 16 + gid) * 66 + k0 + tig + 4]);
        u32 a3 = __float_as_uint(s_k[(mt * 16 + gid + 8) * 66 + k0 + tig + 4]);
#pragma unroll
        for (int j = 0; j < 5; j++) {
            int e0 = (nt0 + j) * 8;
            u32 b0 = __float_as_uint(s_q[(e0 + gid) * 66 + k0 + tig]);
            u32 b1 = __float_as_uint(s_q[(e0 + gid) * 66 + k0 + tig + 4]);
            mma_tf32(c[j], a0, a1, a2, a3, b0, b1);
        }
    }
    __syncthreads();
    float* s_o = sm;                 // [64][161] (reuse)
#pragma unroll
    for (int j = 0; j < 5; j++) {
        int e = (nt0 + j) * 8 + 2 * tig;
        s_o[(mt * 16 + gid) * 161 + e] = c[j][0];
        s_o[(mt * 16 + gid) * 161 + e + 1] = c[j][1];
        s_o[(mt * 16 + gid + 8) * 161 + e] = c[j][2];
        s_o[(mt * 16 + gid + 8) * 161 + e + 1] = c[j][3];
    }
    __syncthreads();
    float inv0 = 1.f / __ldg(s0p);
    if (tid < 160) {
        float zsum = 0.f;
#pragma unroll 8
        for (int t = 0; t < 64; t++) zsum += __expf(s_o[t * 161 + tid] * inv0);
        atomicAdd(&g_Z[bh * E_ + tid], zsum);
    }
    size_t base = ((size_t)bh * N_ + n0) * E_;
#pragma unroll
    for (int i = 0; i < 20; i++) {
        int idx = tid + 512 * i, t = idx / 160, e = idx - t * 160;
        g_logits[base + idx] = s_o[t * 161 + e];
    }
}

// slots via tf32 mma, transposed roles: A = x^T (hd-major), B = probs.
__global__ __launch_bounds__(512) void k_slots(const float* __restrict__ x,
                                               const float* __restrict__ s0p) {
    __shared__ float s_p[32 * 168];   // [n][e]
    __shared__ float s_xT[64 * 36];   // [hd][n]
    int tid = threadIdx.x, bh = blockIdx.x, nc = blockIdx.y;
    int b = bh / H_, h = bh % H_;
    float inv0 = 1.f / __ldg(s0p);
    int w = tid >> 5, lane = tid & 31, gid = lane >> 2, tig = lane & 3;
    int mt = w & 3, ng = w >> 2;
    float c[5][4];
#pragma unroll
    for (int j = 0; j < 5; j++)
#pragma unroll
        for (int q = 0; q < 4; q++) c[j][q] = 0.f;
    for (int sb = 0; sb < 16; sb++) {
        int nb = nc * 512 + sb * 32;
        __syncthreads();
#pragma unroll
        for (int i = 0; i < 10; i++) {
            int idx = tid + 512 * i;
            int n = idx / 160, e = idx - n * 160;
            float l = g_logits[((size_t)bh * N_ + nb + n) * E_ + e];
            s_p[n * 168 + e] = tf32r(__expf(l * inv0));
        }
#pragma unroll
        for (int i = 0; i < 4; i++) {
            int idx = tid + 512 * i, n = idx >> 6, d = idx & 63;
            s_xT[d * 36 + n] = tf32r(x[((size_t)(b * N_ + nb + n)) * D_ + h * HD_ + d]);
        }
        __syncthreads();
#pragma unroll
        for (int ks = 0; ks < 4; ks++) {
            int k0 = ks * 8;
            u32 a0 = __float_as_uint(s_xT[(mt * 16 + gid) * 36 + k0 + tig]);
            u32 a1 = __float_as_uint(s_xT[(mt * 16 + gid + 8) * 36 + k0 + tig]);
            u32 a2 = __float_as_uint(s_xT[(mt * 16 + gid) * 36 + k0 + tig + 4]);
            u32 a3 = __float_as_uint(s_xT[(mt * 16 + gid + 8) * 36 + k0 + tig + 4]);
#pragma unroll
            for (int j = 0; j < 5; j++) {
                int e0 = (ng * 5 + j) * 8;
                u32 b0 = __float_as_uint(s_p[(k0 + tig) * 168 + e0 + gid]);
                u32 b1 = __float_as_uint(s_p[(k0 + tig + 4) * 168 + e0 + gid]);
                mma_tf32(c[j], a0, a1, a2, a3, b0, b1);
            }
        }
    }
#pragma unroll
    for (int j = 0; j < 5; j++) {
        int e = (ng * 5 + j) * 8 + 2 * tig;
        int hd = mt * 16 + gid;
        atomicAdd(&g_slots[((size_t)(b * E_ + e)) * D_ + h * HD_ + hd], c[j][0]);
        atomicAdd(&g_slots[((size_t)(b * E_ + e + 1)) * D_ + h * HD_ + hd], c[j][1]);
        atomicAdd(&g_slots[((size_t)(b * E_ + e)) * D_ + h * HD_ + hd + 8], c[j][2]);
        atomicAdd(&g_slots[((size_t)(b * E_ + e + 1)) * D_ + h * HD_ + hd + 8], c[j][3]);
    }
}

// unified MLP layer1: pre-packed u64 inputs in smem
__global__ __launch_bounds__(128) void k_mlp1u(const float* __restrict__ cw1,
                                               const float* __restrict__ cb1,
                                               const float* __restrict__ ow1,
                                               const float* __restrict__ ob1) {
    __shared__ u64 s_in2[4 * 768];
    int bx = blockIdx.x, tid = threadIdx.x;
    const float *w1, *b1;
    float* o;
    int M, El, e0, e, t;
    if (bx < 192) { e = bx / 6; t = bx % 6; w1 = cw1; b1 = cb1; M = CH_; El = NC_; e0 = 0; o = g_hid; }
    else { int i = bx - 192; e = i >> 1; t = i & 1; w1 = ow1; b1 = ob1; M = OH_; El = NU_; e0 = NC_; o = g_hid2; }
    for (int idx = tid; idx < 4 * 768; idx += 128) {
        int b = idx / 768, d = idx - b * 768;
        float z = g_Z[(b * H_ + (d >> 6)) * E_ + e0 + e];
        float v = g_slots[((size_t)(b * E_ + e0 + e)) * D_ + d] / z;
        s_in2[idx] = pack2(v, v);
    }
    __syncthreads();
    int m = (t * 128 + tid) * 4;
    if (m >= M) return;
    u64 acc[4][2];
#pragma unroll
    for (int bb = 0; bb < 4; bb++) { acc[bb][0] = 0ull; acc[bb][1] = 0ull; }
    size_t st4 = M >> 2;
    const float4* wp = (const float4*)w1 + (size_t)e * 768 * st4 + (m >> 2);
#pragma unroll 1
    for (int k0 = 0; k0 < 768; k0 += 8) {
        float4 wv[8];
#pragma unroll
        for (int i = 0; i < 8; i++) wv[i] = wp[(size_t)(k0 + i) * st4];
#pragma unroll
        for (int i = 0; i < 8; i++) {
            u64 wlo = pack2(wv[i].x, wv[i].y), whi = pack2(wv[i].z, wv[i].w);
#pragma unroll
            for (int bb = 0; bb < 4; bb++) {
                u64 sp = s_in2[bb * 768 + k0 + i];
                ffma2(acc[bb][0], wlo, sp);
                ffma2(acc[bb][1], whi, sp);
            }
        }
    }
    float4 bv = *(const float4*)(b1 + (size_t)e * M + m);
#pragma unroll
    for (int bb = 0; bb < 4; bb++) {
        float a0, a1, a2, a3;
        unpack2(acc[bb][0], a0, a1);
        unpack2(acc[bb][1], a2, a3);
        float4 r;
        r.x = gelu_exact(a0 + bv.x);
        r.y = gelu_exact(a1 + bv.y);
        r.z = gelu_exact(a2 + bv.z);
        r.w = gelu_exact(a3 + bv.w);
        *(float4*)(o + ((size_t)(bb * El + e)) * M + m) = r;
    }
}

// unified MLP layer2: pre-packed u64 hidden, K-split, atomics into g_eo
__global__ __launch_bounds__(128) void k_mlp2u(const float* __restrict__ cw2,
                                               const float* __restrict__ cb2,
                                               const float* __restrict__ ow2,
                                               const float* __restrict__ ob2) {
    __shared__ u64 s_h2[4 * 768];
    int bx = blockIdx.x, tid = threadIdx.x;
    const float *w2, *b2, *hid;
    int K, El, e0, e, t, ks;
    if (bx < 256) { e = bx >> 3; t = (bx >> 2) & 1; ks = bx & 3; w2 = cw2; b2 = cb2; K = CH_; El = NC_; e0 = 0; hid = g_hid; }
    else { int i = bx - 256; e = i >> 1; t = i & 1; ks = 0; w2 = ow2; b2 = ob2; K = OH_; El = NU_; e0 = NC_; hid = g_hid2; }
    for (int idx = tid; idx < 4 * 768; idx += 128) {
        int b = idx / 768, d = idx - b * 768;
        float v = hid[((size_t)(b * El + e)) * K + ks * 768 + d];
        s_h2[idx] = pack2(v, v);
    }
    __syncthreads();
    int m = (t * 128 + tid) * 4;
    if (m >= 768) return;
    u64 acc[4][2];
    float4 bv = make_float4(0.f, 0.f, 0.f, 0.f);
    if (ks == 0) bv = *(const float4*)(b2 + (size_t)e * 768 + m);
#pragma unroll
    for (int bb = 0; bb < 4; bb++) {
        acc[bb][0] = pack2(bv.x, bv.y);
        acc[bb][1] = pack2(bv.z, bv.w);
    }
    const float4* wp = (const float4*)w2 + ((size_t)e * K + ks * 768) * 192 + (m >> 2);
#pragma unroll 1
    for (int k0 = 0; k0 < 768; k0 += 8) {
        float4 wv[8];
#pragma unroll
        for (int i = 0; i < 8; i++) wv[i] = wp[(size_t)(k0 + i) * 192];
#pragma unroll
        for (int i = 0; i < 8; i++) {
            u64 wlo = pack2(wv[i].x, wv[i].y), whi = pack2(wv[i].z, wv[i].w);
#pragma unroll
            for (int bb = 0; bb < 4; bb++) {
                u64 sp = s_h2[bb * 768 + k0 + i];
                ffma2(acc[bb][0], wlo, sp);
                ffma2(acc[bb][1], whi, sp);
            }
        }
    }
#pragma unroll
    for (int bb = 0; bb < 4; bb++) {
        float a0, a1, a2, a3;
        unpack2(acc[bb][0], a0, a1);
        unpack2(acc[bb][1], a2, a3);
        float* dst = &g_eo[((size_t)(bb * E_ + e0 + e)) * D_ + m];
        atomicAdd(dst + 0, a0);
        atomicAdd(dst + 1, a1);
        atomicAdd(dst + 2, a2);
        atomicAdd(dst + 3, a3);
    }
}

// fused entmax15 + combine GEMM; quad-per-token entmax, FIXED iteration count
// (no data-dependent break: quads in a warp would diverge while shuffles use
// the full-warp mask -> hang. 18 uniform iterations, dt ~ 0 after convergence.)
__global__ __launch_bounds__(256) void k_combine(float* __restrict__ out,
                                                 const float* __restrict__ s1p) {
    extern __shared__ float sm[];
    float* s_eoT = sm;              // [64 hd][162]
    float* s_w = sm + 64 * 162;     // [64 t][160]
    int tid = threadIdx.x;
    int n0 = blockIdx.x * 64, bh = blockIdx.y, b = bh / H_, h = bh % H_;
#pragma unroll
    for (int i = 0; i < 40; i++) {
        int idx = tid + 256 * i, e = idx >> 6, hd = idx & 63;
        s_eoT[hd * 162 + e] = g_eo[((size_t)(b * E_ + e)) * D_ + h * HD_ + hd];
    }
    float inv1 = 1.f / __ldg(s1p);
    {
        int qlane = tid & 3, t = tid >> 2;   // quad per token, 64 tokens
        const float* lp = g_logits + ((size_t)bh * N_ + n0 + t) * E_ + qlane * 40;
        float4 vv[10];
#pragma unroll
        for (int j = 0; j < 10; j++) {
            float4 r = *(const float4*)(lp + j * 4);
            vv[j].x = r.x * inv1; vv[j].y = r.y * inv1;
            vv[j].z = r.z * inv1; vv[j].w = r.w * inv1;
        }
        float mx = -1e30f;
#pragma unroll
        for (int j = 0; j < 10; j++)
            mx = fmaxf(mx, fmaxf(fmaxf(vv[j].x, vv[j].y), fmaxf(vv[j].z, vv[j].w)));
        mx = fmaxf(mx, __shfl_xor_sync(~0u, mx, 1));
        mx = fmaxf(mx, __shfl_xor_sync(~0u, mx, 2));
#pragma unroll
        for (int j = 0; j < 10; j++) {
            vv[j].x = (vv[j].x - mx) * 0.5f; vv[j].y = (vv[j].y - mx) * 0.5f;
            vv[j].z = (vv[j].z - mx) * 0.5f; vv[j].w = (vv[j].w - mx) * 0.5f;
        }
        float tau = -1.f;                    // Newton from left: f convex decreasing
#pragma unroll 1
        for (int it = 0; it < 18; it++) {
            float s1 = 0.f, s2 = 0.f;
#pragma unroll
            for (int j = 0; j < 10; j++) {
                float d0 = fmaxf(vv[j].x - tau, 0.f), d1 = fmaxf(vv[j].y - tau, 0.f);
                float d2 = fmaxf(vv[j].z - tau, 0.f), d3 = fmaxf(vv[j].w - tau, 0.f);
                s1 += d0 + d1 + d2 + d3;
                s2 = fmaf(d0, d0, s2); s2 = fmaf(d1, d1, s2);
                s2 = fmaf(d2, d2, s2); s2 = fmaf(d3, d3, s2);
            }
            s1 += __shfl_xor_sync(~0u, s1, 1);
            s1 += __shfl_xor_sync(~0u, s1, 2);
            s2 += __shfl_xor_sync(~0u, s2, 1);
            s2 += __shfl_xor_sync(~0u, s2, 2);
            tau += (s2 - 1.f) / (2.f * s1);
        }
        float* wp = s_w + t * 160 + qlane * 40;
#pragma unroll
        for (int j = 0; j < 10; j++) {
            float d0 = fmaxf(vv[j].x - tau, 0.f), d1 = fmaxf(vv[j].y - tau, 0.f);
            float d2 = fmaxf(vv[j].z - tau, 0.f), d3 = fmaxf(vv[j].w - tau, 0.f);
            float4 r = make_float4(d0 * d0, d1 * d1, d2 * d2, d3 * d3);
            *(float4*)(wp + j * 4) = r;
        }
    }
    __syncthreads();
    int hq = tid & 15, tq = tid >> 4;
    u64 acc[4][4];
#pragma unroll
    for (int tt = 0; tt < 4; tt++)
#pragma unroll
        for (int c = 0; c < 4; c++) acc[tt][c] = 0ull;
#pragma unroll 2
    for (int ep = 0; ep < 80; ep++) {
        u64 wv[4], ev[4];
#pragma unroll
        for (int tt = 0; tt < 4; tt++) wv[tt] = *(const u64*)(s_w + (tq * 4 + tt) * 160 + 2 * ep);
#pragma unroll
        for (int c = 0; c < 4; c++) ev[c] = *(const u64*)(s_eoT + (hq * 4 + c) * 162 + 2 * ep);
#pragma unroll
        for (int tt = 0; tt < 4; tt++)
#pragma unroll
            for (int c = 0; c < 4; c++) ffma2(acc[tt][c], wv[tt], ev[c]);
    }
#pragma unroll
    for (int tt = 0; tt < 4; tt++) {
        float4 r = make_float4(sum2(acc[tt][0]), sum2(acc[tt][1]),
                               sum2(acc[tt][2]), sum2(acc[tt][3]));
        *(float4*)(out + ((size_t)(b * N_ + n0 + tq * 4 + tt)) * D_ + h * HD_ + hq * 4) = r;
    }
}

extern "C" void kernel_launch(void* const* d_in, const int* in_sizes, int n_in,
                              void* d_out, int out_size) {
    const float* x   = (const float*)d_in[0];
    const float* phi = (const float*)d_in[1];
    const float* kgm = (const float*)d_in[2];
    const float* kbt = (const float*)d_in[3];
    const float* qgm = (const float*)d_in[4];
    const float* qbt = (const float*)d_in[5];
    const float* lnw = (const float*)d_in[6];
    const float* lnb = (const float*)d_in[7];
    const float* s0  = (const float*)d_in[8];
    const float* s1  = (const float*)d_in[9];
    const float* cw1 = (const float*)d_in[10];
    const float* cb1 = (const float*)d_in[11];
    const float* cw2 = (const float*)d_in[12];
    const float* cb2 = (const float*)d_in[13];
    const float* ow1 = (const float*)d_in[14];
    const float* ob1 = (const float*)d_in[15];
    const float* ow2 = (const float*)d_in[16];
    const float* ob2 = (const float*)d_in[17];
    float* out = (float*)d_out;

    const int SM_LOG = (64 * 66 + 160 * 66 + 64) * 4;
    const int SM_CMB = (64 * 162 + 64 * 160) * 4;
    cudaFuncSetAttribute(k_logits, cudaFuncAttributeMaxDynamicSharedMemorySize, SM_LOG);
    cudaFuncSetAttribute(k_combine, cudaFuncAttributeMaxDynamicSharedMemorySize, SM_CMB);

    k_zero<<<1920, 256>>>();
    k_prep_q<<<60, 1024>>>(phi, qgm, qbt, lnw, lnb);
    k_logits<<<dim3(64, 48), 512, SM_LOG>>>(x, kgm, kbt, s0);
    k_slots<<<dim3(48, 8), 512>>>(x, s0);
    k_mlp1u<<<448, 128>>>(cw1, cb1, ow1, ob1);
    k_mlp2u<<<512, 128>>>(cw2, cb2, ow2, ob2);
    k_combine<<<dim3(64, 48), 256, SM_CMB>>>(out, s1);
}